// round 8
// baseline (speedup 1.0000x reference)
#include <cuda_runtime.h>
#include <cstdint>

// Problem constants
#define NB     32      // batch rows per CTA
#define TPB    256     // threads per CTA
#define NCTA   128     // 128 * 32 = 4096 batch
#define HD     128     // hidden units H
#define DD     64      // latent dim D
#define G4     512     // 4*H gate width
#define KT     16      // k-tile rows for weight streaming
#define TILEF  (KT * G4)   // 8192 floats = 32KB per tile
#define NTAU   28      // tiles per step: 4 (Wk0) + 8 (Wr0) + 8 (Wk1) + 8 (Wr1)
#define TWARM  50
#define NSTEPS 149     // 50 warmup + 99 AR lstm steps
#define TOUT   100

typedef unsigned long long ull;

// ---------------- async copy helpers ----------------
__device__ __forceinline__ void cp_async16(void* dst, const void* src) {
    unsigned d = (unsigned)__cvta_generic_to_shared(dst);
    asm volatile("cp.async.cg.shared.global [%0], [%1], 16;\n" :: "r"(d), "l"(src));
}
__device__ __forceinline__ void cp_commit() { asm volatile("cp.async.commit_group;\n" ::); }
__device__ __forceinline__ void cp_wait1()  { asm volatile("cp.async.wait_group 1;\n" ::: "memory"); }

// ---------------- packed f32x2 helpers ----------------
__device__ __forceinline__ ull pack_dup(float v) {
    ull r; asm("mov.b64 %0, {%1, %1};" : "=l"(r) : "f"(v)); return r;
}
__device__ __forceinline__ ull pack2(float x, float y) {
    ull r; asm("mov.b64 %0, {%1, %2};" : "=l"(r) : "f"(x), "f"(y)); return r;
}
__device__ __forceinline__ float2 unpack2(ull p) {
    float2 r; asm("mov.b64 {%0, %1}, %2;" : "=f"(r.x), "=f"(r.y) : "l"(p)); return r;
}
__device__ __forceinline__ void fma2(ull& d, ull a, ull b) {
    asm("fma.rn.f32x2 %0, %1, %2, %0;" : "+l"(d) : "l"(a), "l"(b));
}

// ---------------- fast activations (MUFU-based, ~1e-6 rel err) ----------------
__device__ __forceinline__ float sig_f(float x) {
    return __fdividef(1.0f, 1.0f + __expf(-x));
}
__device__ __forceinline__ float tanh_f(float x) {
    return 1.0f - __fdividef(2.0f, __expf(2.0f * x) + 1.0f);
}

// W tile base pointer for tile index tau in [0, 28)
__device__ __forceinline__ const float* tile_w(int tau,
    const float* Wk0, const float* Wr0, const float* Wk1, const float* Wr1)
{
    if (tau < 4)  return Wk0 + tau * TILEF;
    if (tau < 12) return Wr0 + (tau - 4) * TILEF;
    if (tau < 20) return Wk1 + (tau - 12) * TILEF;
    return Wr1 + (tau - 20) * TILEF;
}

// Load one KT x G4 fp32 weight tile (contiguous 32KB) global -> smem via cp.async
__device__ __forceinline__ void load_tile(float* buf, const float* __restrict__ src, int tid) {
#pragma unroll
    for (int i = 0; i < (KT * G4) / (4 * TPB); ++i) {   // 8 x 16B per thread
        int idx = (i * TPB + tid) * 4;
        cp_async16(buf + idx, src + idx);
    }
}

// acc[8][4] (f32x2) += A[rows tb*8..][aoff..aoff+KT) * Wtile(KT x 512)
__device__ __forceinline__ void compute_tile(
    ull acc[8][4], const float* __restrict__ As, int astride, int aoff,
    const float* __restrict__ wt, int tb, int tj0)
{
#pragma unroll
    for (int kk4 = 0; kk4 < KT; kk4 += 4) {
        float a[8][4];
#pragma unroll
        for (int i = 0; i < 8; ++i) {
            float4 av = *(const float4*)&As[(tb * 8 + i) * astride + aoff + kk4];
            a[i][0] = av.x; a[i][1] = av.y; a[i][2] = av.z; a[i][3] = av.w;
        }
#pragma unroll
        for (int u = 0; u < 4; ++u) {
            ull wv[4];
#pragma unroll
            for (int g = 0; g < 4; ++g)
                wv[g] = *(const ull*)&wt[(kk4 + u) * G4 + g * HD + tj0 * 2];
#pragma unroll
            for (int i = 0; i < 8; ++i) {
                ull ad = pack_dup(a[i][u]);
#pragma unroll
                for (int g = 0; g < 4; ++g)
                    fma2(acc[i][g], ad, wv[g]);
            }
        }
    }
}

// gate activations + cell update + h store
__device__ __forceinline__ void lstm_epilogue(
    ull acc[8][4], float c[8][2], float* __restrict__ hs, int tb, int tj0)
{
#pragma unroll
    for (int i = 0; i < 8; ++i) {
        float2 iv = unpack2(acc[i][0]);
        float2 fv = unpack2(acc[i][1]);
        float2 gv = unpack2(acc[i][2]);
        float2 ov = unpack2(acc[i][3]);
        float cx = fmaf(sig_f(fv.x), c[i][0], sig_f(iv.x) * tanh_f(gv.x));
        float cy = fmaf(sig_f(fv.y), c[i][1], sig_f(iv.y) * tanh_f(gv.y));
        c[i][0] = cx; c[i][1] = cy;
        float2 h = make_float2(sig_f(ov.x) * tanh_f(cx), sig_f(ov.y) * tanh_f(cy));
        *(float2*)&hs[(tb * 8 + i) * HD + tj0 * 2] = h;
    }
}

__device__ __forceinline__ void init_acc(ull acc[8][4], const float* __restrict__ bs, int tj0) {
    ull bv[4];
#pragma unroll
    for (int g = 0; g < 4; ++g) {
        float2 b2 = *(const float2*)&bs[g * HD + tj0 * 2];
        bv[g] = pack2(b2.x, b2.y);
    }
#pragma unroll
    for (int i = 0; i < 8; ++i)
#pragma unroll
        for (int g = 0; g < 4; ++g) acc[i][g] = bv[g];
}

extern "C" __global__ void __launch_bounds__(TPB, 1)
lstm_rollout_kernel(const float* __restrict__ x,
                    const float* __restrict__ Wk0, const float* __restrict__ Wr0, const float* __restrict__ b0,
                    const float* __restrict__ Wk1, const float* __restrict__ Wr1, const float* __restrict__ b1,
                    const float* __restrict__ Wd,  const float* __restrict__ bd,
                    float* __restrict__ out)
{
    extern __shared__ float sm[];
    float* wbuf = sm;                        // [3][KT*G4]    24576 f (96KB)
    float* xs   = wbuf + 3 * TILEF;          // [NB][DD]       2048 f  (input / pred)
    float* h0s  = xs   + NB * DD;            // [NB][HD]       4096 f
    float* h1s  = h0s  + NB * HD;            // [NB][HD]       4096 f
    float* wds  = h1s  + NB * HD;            // [HD][DD]       8192 f  (resident Wd)
    float* b0s  = wds  + HD * DD;            // [G4]
    float* b1s  = b0s  + G4;                 // [G4]
    float* bds  = b1s  + G4;                 // [DD]

    const int tid = threadIdx.x;
    const int tj0 = tid & 63;                // 64 col-threads, 2 cols/gate each
    const int tb  = tid >> 6;                // 4 row-groups, 8 rows each
    const int gb0 = blockIdx.x * NB;

    // resident weights / biases, zero states
    for (int i = tid; i < HD * DD; i += TPB) wds[i] = Wd[i];
    for (int i = tid; i < G4; i += TPB) { b0s[i] = b0[i]; b1s[i] = b1[i]; }
    if (tid < DD) bds[tid] = bd[tid];
    for (int i = tid; i < NB * HD; i += TPB) { h0s[i] = 0.0f; h1s[i] = 0.0f; }

    float c0r[8][2], c1r[8][2];
#pragma unroll
    for (int i = 0; i < 8; ++i)
#pragma unroll
        for (int j = 0; j < 2; ++j) { c0r[i][j] = 0.0f; c1r[i][j] = 0.0f; }

    // prologue: prefetch tiles 0,1 into ring buffers 0,1 (one commit group per tile)
    load_tile(wbuf + 0 * TILEF, tile_w(0, Wk0, Wr0, Wk1, Wr1), tid); cp_commit();
    load_tile(wbuf + 1 * TILEF, tile_w(1, Wk0, Wr0, Wk1, Wr1), tid); cp_commit();
    __syncthreads();   // smem init visible

    int bufc = 0;      // ring buffer cursor (mod 3), free-running across steps

#pragma unroll 1
    for (int step = 0; step < NSTEPS; ++step) {
        // ---- input: warmup reads x[:, step, :]; AR phase reuses xs (= previous pred)
        // (visibility to other threads is covered by the tau=0 tile barrier)
        if (step < TWARM) {
#pragma unroll
            for (int i = 0; i < (NB * DD) / TPB; ++i) {
                int idx = i * TPB + tid;
                int b = idx >> 6, d = idx & 63;
                xs[idx] = x[((size_t)(gb0 + b) * TWARM + step) * DD + d];
            }
        }

        ull acc[8][4];
        const float* A = xs;
        int as = DD, aoff = 0;

#pragma unroll 1
        for (int tau = 0; tau < NTAU; ++tau) {
            if (tau == 0)       { A = xs;  as = DD; aoff = 0; init_acc(acc, b0s, tj0); }
            else if (tau == 4)  { A = h0s; as = HD; aoff = 0; }
            else if (tau == 12) { A = h0s; as = HD; aoff = 0; init_acc(acc, b1s, tj0); }
            else if (tau == 20) { A = h1s; as = HD; aoff = 0; }

            cp_wait1();          // tile tau's group complete (tau+1 may stay pending)
            __syncthreads();     // tau's data visible to all; frees buffer (bufc+2)%3

            {   // prefetch tile tau+2 (wraps into next step's stream)
                int tn = tau + 2; if (tn >= NTAU) tn -= NTAU;
                int bn = bufc + 2; if (bn >= 3) bn -= 3;
                load_tile(wbuf + bn * TILEF, tile_w(tn, Wk0, Wr0, Wk1, Wr1), tid);
                cp_commit();
            }

            compute_tile(acc, A, as, aoff, wbuf + bufc * TILEF, tb, tj0);
            aoff += KT;
            bufc = (bufc == 2) ? 0 : bufc + 1;

            if (tau == 11) {            // layer-0 epilogue
                __syncthreads();        // all old-h0 reads done before overwrite
                lstm_epilogue(acc, c0r, h0s, tb, tj0);
            } else if (tau == 27) {     // layer-1 epilogue
                __syncthreads();        // all old-h1 reads done before overwrite
                lstm_epilogue(acc, c1r, h1s, tb, tj0);
            }
        }

        // ============ dense decode: pred = h1 @ Wd + bd (steps >= 49) ============
        if (step >= TWARM - 1) {
            __syncthreads();            // h1s writes visible before cross-thread reads
            const int s = step - (TWARM - 1);         // 0..99
            float dacc[8];
            const float bw = bds[tj0];
#pragma unroll
            for (int i = 0; i < 8; ++i) dacc[i] = bw;
#pragma unroll 4
            for (int k4 = 0; k4 < HD; k4 += 4) {
                float a[8][4];
#pragma unroll
                for (int i = 0; i < 8; ++i) {
                    float4 av = *(const float4*)&h1s[(tb * 8 + i) * HD + k4];
                    a[i][0] = av.x; a[i][1] = av.y; a[i][2] = av.z; a[i][3] = av.w;
                }
#pragma unroll
                for (int u = 0; u < 4; ++u) {
                    float w = wds[(k4 + u) * DD + tj0];
#pragma unroll
                    for (int i = 0; i < 8; ++i)
                        dacc[i] = fmaf(a[i][u], w, dacc[i]);
                }
            }
#pragma unroll
            for (int i = 0; i < 8; ++i) {
                xs[(tb * 8 + i) * DD + tj0] = dacc[i];            // feed next step
                out[((size_t)(gb0 + tb * 8 + i) * TOUT + s) * DD + tj0] = dacc[i];
            }
            // no trailing sync: next step's tau=0 barrier orders xs reads
        }
    }
}

extern "C" void kernel_launch(void* const* d_in, const int* in_sizes, int n_in,
                              void* d_out, int out_size)
{
    const float* x   = (const float*)d_in[0];
    const float* Wk0 = (const float*)d_in[1];
    const float* Wr0 = (const float*)d_in[2];
    const float* b0  = (const float*)d_in[3];
    const float* Wk1 = (const float*)d_in[4];
    const float* Wr1 = (const float*)d_in[5];
    const float* b1  = (const float*)d_in[6];
    const float* Wd  = (const float*)d_in[7];
    const float* bd  = (const float*)d_in[8];

    size_t smem = (size_t)(3 * TILEF + NB * DD + 2 * NB * HD + HD * DD + 2 * G4 + DD) * sizeof(float);
    cudaFuncSetAttribute(lstm_rollout_kernel,
                         cudaFuncAttributeMaxDynamicSharedMemorySize, (int)smem);
    lstm_rollout_kernel<<<NCTA, TPB, smem>>>(x, Wk0, Wr0, b0, Wk1, Wr1, b1, Wd, bd,
                                             (float*)d_out);
}

// round 11
// speedup vs baseline: 1.5576x; 1.5576x over previous
#include <cuda_runtime.h>
#include <cstdint>

// Problem constants
#define NB     32      // batch rows per CTA
#define TPB    512     // threads per CTA (16 warps -> 4 per SMSP)
#define NCTA   128     // 128 * 32 = 4096 batch
#define HD     128     // hidden units H
#define DD     64      // latent dim D
#define G4     512     // 4*H gate width
#define KT     16      // k-tile rows for weight streaming
#define TWARM  50
#define NSTEPS 149     // 50 warmup + 99 AR lstm steps
#define TOUT   100

typedef unsigned long long ull;

// ---------------- async copy helpers ----------------
__device__ __forceinline__ void cp_async16(void* dst, const void* src) {
    unsigned d = (unsigned)__cvta_generic_to_shared(dst);
    asm volatile("cp.async.cg.shared.global [%0], [%1], 16;\n" :: "r"(d), "l"(src));
}
__device__ __forceinline__ void cp_commit() { asm volatile("cp.async.commit_group;\n" ::); }
__device__ __forceinline__ void cp_wait1()  { asm volatile("cp.async.wait_group 1;\n" ::: "memory"); }
__device__ __forceinline__ void cp_wait0()  { asm volatile("cp.async.wait_group 0;\n" ::: "memory"); }

// ---------------- packed f32x2 helpers ----------------
__device__ __forceinline__ ull pack_dup(float v) {
    ull r; asm("mov.b64 %0, {%1, %1};" : "=l"(r) : "f"(v)); return r;
}
__device__ __forceinline__ ull pack2(float x, float y) {
    ull r; asm("mov.b64 %0, {%1, %2};" : "=l"(r) : "f"(x), "f"(y)); return r;
}
__device__ __forceinline__ float2 unpack2(ull p) {
    float2 r; asm("mov.b64 {%0, %1}, %2;" : "=f"(r.x), "=f"(r.y) : "l"(p)); return r;
}
__device__ __forceinline__ void fma2(ull& d, ull a, ull b) {
    asm("fma.rn.f32x2 %0, %1, %2, %0;" : "+l"(d) : "l"(a), "l"(b));
}

// ---------------- fast activations (MUFU-based, ~1e-6 rel err) ----------------
__device__ __forceinline__ float sig_f(float x) {
    return __fdividef(1.0f, 1.0f + __expf(-x));
}
__device__ __forceinline__ float tanh_f(float x) {
    return 1.0f - __fdividef(2.0f, __expf(2.0f * x) + 1.0f);
}

// Load one KT x G4 fp32 weight tile (contiguous 32KB) global -> smem via cp.async
__device__ __forceinline__ void load_tile(float* buf, const float* __restrict__ src, int tid) {
#pragma unroll
    for (int i = 0; i < (KT * G4) / (4 * TPB); ++i) {   // 4 x 16B per thread
        int idx = (i * TPB + tid) * 4;
        cp_async16(buf + idx, src + idx);
    }
}

// acc[4][4] (f32x2 pairs) += A[NB x astride] * W(NT*KT x 512)
// thread (tb, tj0): rows tb*4 .. tb*4+3, cols { g*128 + tj0*2, +1 : g in 0..3 }
__device__ __forceinline__ void gemm_part(
    ull acc[4][4], const float* __restrict__ As, int astride,
    const float* __restrict__ Wg, int NT,
    float* wbuf, int tid, int tb, int tj0)
{
    load_tile(wbuf, Wg, tid);
    cp_commit();
#pragma unroll 1
    for (int t = 0; t < NT; ++t) {
        if (t + 1 < NT) {
            load_tile(wbuf + ((t + 1) & 1) * (KT * G4), Wg + (t + 1) * (KT * G4), tid);
            cp_commit();
            cp_wait1();
        } else {
            cp_wait0();
        }
        __syncthreads();
        const float* wt = wbuf + (t & 1) * (KT * G4);
        const int k0 = t * KT;
#pragma unroll
        for (int kk4 = 0; kk4 < KT; kk4 += 4) {
            float a[4][4];
#pragma unroll
            for (int i = 0; i < 4; ++i) {
                float4 av = *(const float4*)&As[(tb * 4 + i) * astride + k0 + kk4];
                a[i][0] = av.x; a[i][1] = av.y; a[i][2] = av.z; a[i][3] = av.w;
            }
#pragma unroll
            for (int u = 0; u < 4; ++u) {
                ull wv[4];
#pragma unroll
                for (int g = 0; g < 4; ++g)
                    wv[g] = *(const ull*)&wt[(kk4 + u) * G4 + g * HD + tj0 * 2];
#pragma unroll
                for (int i = 0; i < 4; ++i) {
                    ull ad = pack_dup(a[i][u]);
#pragma unroll
                    for (int g = 0; g < 4; ++g)
                        fma2(acc[i][g], ad, wv[g]);
                }
            }
        }
        __syncthreads();
    }
}

extern "C" __global__ void __launch_bounds__(TPB, 1)
lstm_rollout_kernel(const float* __restrict__ x,
                    const float* __restrict__ Wk0, const float* __restrict__ Wr0, const float* __restrict__ b0,
                    const float* __restrict__ Wk1, const float* __restrict__ Wr1, const float* __restrict__ b1,
                    const float* __restrict__ Wd,  const float* __restrict__ bd,
                    float* __restrict__ out)
{
    extern __shared__ float sm[];
    float* wbuf = sm;                        // [2][KT*G4]    16384 f
    float* xs   = wbuf + 2 * KT * G4;        // [NB][DD]       2048 f  (input / pred)
    float* h0s  = xs   + NB * DD;            // [NB][HD]       4096 f
    float* h1s  = h0s  + NB * HD;            // [NB][HD]       4096 f
    float* wds  = h1s  + NB * HD;            // [HD][DD]       8192 f  (resident Wd)
    float* b0s  = wds  + HD * DD;            // [G4]
    float* b1s  = b0s  + G4;                 // [G4]
    float* bds  = b1s  + G4;                 // [DD]

    const int tid = threadIdx.x;
    const int tj0 = tid & 63;                // 64 col-threads, 2 cols/gate each
    const int tb  = tid >> 6;                // 8 row-groups, 4 rows each
    const int gb0 = blockIdx.x * NB;

    // resident weights / biases, zero states
    for (int i = tid; i < HD * DD; i += TPB) wds[i] = Wd[i];
    for (int i = tid; i < G4; i += TPB) { b0s[i] = b0[i]; b1s[i] = b1[i]; }
    if (tid < DD) bds[tid] = bd[tid];
    for (int i = tid; i < NB * HD; i += TPB) { h0s[i] = 0.0f; h1s[i] = 0.0f; }

    float c0r[4][2], c1r[4][2];
#pragma unroll
    for (int i = 0; i < 4; ++i)
#pragma unroll
        for (int j = 0; j < 2; ++j) { c0r[i][j] = 0.0f; c1r[i][j] = 0.0f; }
    __syncthreads();

#pragma unroll 1
    for (int step = 0; step < NSTEPS; ++step) {
        // ---- input: warmup reads x[:, step, :]; AR phase reuses xs (= previous pred)
        if (step < TWARM) {
#pragma unroll
            for (int i = 0; i < (NB * DD) / TPB; ++i) {
                int idx = i * TPB + tid;
                int b = idx >> 6, d = idx & 63;
                xs[idx] = x[((size_t)(gb0 + b) * TWARM + step) * DD + d];
            }
            __syncthreads();
        }

        ull acc[4][4];

        // ================= layer 0 =================
        {
            ull bv[4];
#pragma unroll
            for (int g = 0; g < 4; ++g) {
                float2 b2 = *(const float2*)&b0s[g * HD + tj0 * 2];
                bv[g] = pack2(b2.x, b2.y);
            }
#pragma unroll
            for (int i = 0; i < 4; ++i)
#pragma unroll
                for (int g = 0; g < 4; ++g) acc[i][g] = bv[g];
        }
        gemm_part(acc, xs,  DD, Wk0, DD / KT, wbuf, tid, tb, tj0);   // 4 tiles
        gemm_part(acc, h0s, HD, Wr0, HD / KT, wbuf, tid, tb, tj0);   // 8 tiles
#pragma unroll
        for (int i = 0; i < 4; ++i) {
            float2 iv = unpack2(acc[i][0]);
            float2 fv = unpack2(acc[i][1]);
            float2 gv = unpack2(acc[i][2]);
            float2 ov = unpack2(acc[i][3]);
            float cx = fmaf(sig_f(fv.x), c0r[i][0], sig_f(iv.x) * tanh_f(gv.x));
            float cy = fmaf(sig_f(fv.y), c0r[i][1], sig_f(iv.y) * tanh_f(gv.y));
            c0r[i][0] = cx; c0r[i][1] = cy;
            float2 h = make_float2(sig_f(ov.x) * tanh_f(cx), sig_f(ov.y) * tanh_f(cy));
            *(float2*)&h0s[(tb * 4 + i) * HD + tj0 * 2] = h;
        }
        __syncthreads();

        // ================= layer 1 =================
        {
            ull bv[4];
#pragma unroll
            for (int g = 0; g < 4; ++g) {
                float2 b2 = *(const float2*)&b1s[g * HD + tj0 * 2];
                bv[g] = pack2(b2.x, b2.y);
            }
#pragma unroll
            for (int i = 0; i < 4; ++i)
#pragma unroll
                for (int g = 0; g < 4; ++g) acc[i][g] = bv[g];
        }
        gemm_part(acc, h0s, HD, Wk1, HD / KT, wbuf, tid, tb, tj0);   // 8 tiles
        gemm_part(acc, h1s, HD, Wr1, HD / KT, wbuf, tid, tb, tj0);   // 8 tiles
#pragma unroll
        for (int i = 0; i < 4; ++i) {
            float2 iv = unpack2(acc[i][0]);
            float2 fv = unpack2(acc[i][1]);
            float2 gv = unpack2(acc[i][2]);
            float2 ov = unpack2(acc[i][3]);
            float cx = fmaf(sig_f(fv.x), c1r[i][0], sig_f(iv.x) * tanh_f(gv.x));
            float cy = fmaf(sig_f(fv.y), c1r[i][1], sig_f(iv.y) * tanh_f(gv.y));
            c1r[i][0] = cx; c1r[i][1] = cy;
            float2 h = make_float2(sig_f(ov.x) * tanh_f(cx), sig_f(ov.y) * tanh_f(cy));
            *(float2*)&h1s[(tb * 4 + i) * HD + tj0 * 2] = h;
        }
        __syncthreads();

        // ============ dense decode: pred = h1 @ Wd + bd (steps >= 49) ============
        if (step >= TWARM - 1) {
            const int s = step - (TWARM - 1);         // 0..99
            float dacc[4];
            const float bw = bds[tj0];
#pragma unroll
            for (int i = 0; i < 4; ++i) dacc[i] = bw;
#pragma unroll 4
            for (int k4 = 0; k4 < HD; k4 += 4) {
                float a[4][4];
#pragma unroll
                for (int i = 0; i < 4; ++i) {
                    float4 av = *(const float4*)&h1s[(tb * 4 + i) * HD + k4];
                    a[i][0] = av.x; a[i][1] = av.y; a[i][2] = av.z; a[i][3] = av.w;
                }
#pragma unroll
                for (int u = 0; u < 4; ++u) {
                    float w = wds[(k4 + u) * DD + tj0];
#pragma unroll
                    for (int i = 0; i < 4; ++i)
                        dacc[i] = fmaf(a[i][u], w, dacc[i]);
                }
            }
#pragma unroll
            for (int i = 0; i < 4; ++i) {
                xs[(tb * 4 + i) * DD + tj0] = dacc[i];            // feed next step
                out[((size_t)(gb0 + tb * 4 + i) * TOUT + s) * DD + tj0] = dacc[i];
            }
            __syncthreads();
        }
    }
}

extern "C" void kernel_launch(void* const* d_in, const int* in_sizes, int n_in,
                              void* d_out, int out_size)
{
    const float* x   = (const float*)d_in[0];
    const float* Wk0 = (const float*)d_in[1];
    const float* Wr0 = (const float*)d_in[2];
    const float* b0  = (const float*)d_in[3];
    const float* Wk1 = (const float*)d_in[4];
    const float* Wr1 = (const float*)d_in[5];
    const float* b1  = (const float*)d_in[6];
    const float* Wd  = (const float*)d_in[7];
    const float* bd  = (const float*)d_in[8];

    size_t smem = (size_t)(2 * KT * G4 + NB * DD + 2 * NB * HD + HD * DD + 2 * G4 + DD) * sizeof(float);
    cudaFuncSetAttribute(lstm_rollout_kernel,
                         cudaFuncAttributeMaxDynamicSharedMemorySize, (int)smem);
    lstm_rollout_kernel<<<NCTA, TPB, smem>>>(x, Wk0, Wr0, b0, Wk1, Wr1, b1, Wd, bd,
                                             (float*)d_out);
}

// round 13
// speedup vs baseline: 1.7593x; 1.1295x over previous
#include <cuda_runtime.h>
#include <cstdint>

// Problem constants
#define NB     32      // batch rows per CTA
#define TPB    256     // threads per CTA (8 warps -> 2 per SMSP)
#define NCTA   128     // 128 * 32 = 4096 batch
#define HD     128     // hidden units H
#define DD     64      // latent dim D
#define G4     512     // 4*H gate width
#define KT     16      // k-tile rows for weight streaming
#define TWARM  50
#define NSTEPS 149     // 50 warmup + 99 AR lstm steps
#define TOUT   100

typedef unsigned long long ull;

// ---------------- async copy helpers ----------------
__device__ __forceinline__ void cp_async16(void* dst, const void* src) {
    unsigned d = (unsigned)__cvta_generic_to_shared(dst);
    asm volatile("cp.async.cg.shared.global [%0], [%1], 16;\n" :: "r"(d), "l"(src));
}
__device__ __forceinline__ void cp_commit() { asm volatile("cp.async.commit_group;\n" ::); }
__device__ __forceinline__ void cp_wait0()  { asm volatile("cp.async.wait_group 0;\n" ::: "memory"); }

// ---------------- packed f32x2 helpers ----------------
__device__ __forceinline__ ull pack_dup(float v) {
    ull r; asm("mov.b64 %0, {%1, %1};" : "=l"(r) : "f"(v)); return r;
}
__device__ __forceinline__ ull pack2(float x, float y) {
    ull r; asm("mov.b64 %0, {%1, %2};" : "=l"(r) : "f"(x), "f"(y)); return r;
}
__device__ __forceinline__ float2 unpack2(ull p) {
    float2 r; asm("mov.b64 {%0, %1}, %2;" : "=f"(r.x), "=f"(r.y) : "l"(p)); return r;
}
__device__ __forceinline__ void fma2(ull& d, ull a, ull b) {
    asm("fma.rn.f32x2 %0, %1, %2, %0;" : "+l"(d) : "l"(a), "l"(b));
}

// ---------------- fast activations (MUFU-based, ~1e-6 rel err) ----------------
__device__ __forceinline__ float sig_f(float x) {
    return __fdividef(1.0f, 1.0f + __expf(-x));
}
__device__ __forceinline__ float tanh_f(float x) {
    return 1.0f - __fdividef(2.0f, __expf(2.0f * x) + 1.0f);
}

// Load one KT x G4 fp32 weight tile (contiguous 32KB) global -> smem via cp.async
__device__ __forceinline__ void load_tile(float* buf, const float* __restrict__ src, int tid) {
#pragma unroll
    for (int i = 0; i < (KT * G4) / (4 * TPB); ++i) {   // 8 x 16B per thread
        int idx = (i * TPB + tid) * 4;
        cp_async16(buf + idx, src + idx);
    }
}

// acc[8][4] (f32x2 pairs) += A[NB x astride] * W(NT*KT x 512)
// thread (tb, tj0): rows tb*8 .. tb*8+7, cols { g*128 + tj0*2, +1 : g in 0..3 }
// ONE barrier per tile: prefetch of tile t+1 is issued AFTER the barrier, so the
// buffer it overwrites (holding tile t-1) is provably drained by that barrier.
// Distance-1 prefetch + wait_group 0: tile t's load was issued one full tile-compute
// earlier, so the wait is free except on the first tile of each gemm.
__device__ __forceinline__ void gemm_part(
    ull acc[8][4], const float* __restrict__ As, int astride,
    const float* __restrict__ Wg, int NT,
    float* wbuf, int tid, int tb, int tj0)
{
    load_tile(wbuf, Wg, tid);      // tile 0 -> buf 0
    cp_commit();
#pragma unroll 1
    for (int t = 0; t < NT; ++t) {
        cp_wait0();                 // tile t landed (issued one tile ago)
        __syncthreads();            // tile t visible; all warps done reading buf[(t+1)&1]
        if (t + 1 < NT) {           // prefetch next tile, overlapped with compute below
            load_tile(wbuf + ((t + 1) & 1) * (KT * G4), Wg + (t + 1) * (KT * G4), tid);
            cp_commit();
        }
        const float* wt = wbuf + (t & 1) * (KT * G4);
        const int k0 = t * KT;
#pragma unroll
        for (int kk4 = 0; kk4 < KT; kk4 += 4) {
            float a[8][4];
#pragma unroll
            for (int i = 0; i < 8; ++i) {
                float4 av = *(const float4*)&As[(tb * 8 + i) * astride + k0 + kk4];
                a[i][0] = av.x; a[i][1] = av.y; a[i][2] = av.z; a[i][3] = av.w;
            }
#pragma unroll
            for (int u = 0; u < 4; ++u) {
                ull wv[4];
#pragma unroll
                for (int g = 0; g < 4; ++g)
                    wv[g] = *(const ull*)&wt[(kk4 + u) * G4 + g * HD + tj0 * 2];
#pragma unroll
                for (int i = 0; i < 8; ++i) {
                    ull ad = pack_dup(a[i][u]);
#pragma unroll
                    for (int g = 0; g < 4; ++g)
                        fma2(acc[i][g], ad, wv[g]);
                }
            }
        }
        // no trailing barrier: next iteration's barrier provides the drain point
    }
}

extern "C" __global__ void __launch_bounds__(TPB, 1)
lstm_rollout_kernel(const float* __restrict__ x,
                    const float* __restrict__ Wk0, const float* __restrict__ Wr0, const float* __restrict__ b0,
                    const float* __restrict__ Wk1, const float* __restrict__ Wr1, const float* __restrict__ b1,
                    const float* __restrict__ Wd,  const float* __restrict__ bd,
                    float* __restrict__ out)
{
    extern __shared__ float sm[];
    float* wbuf = sm;                        // [2][KT*G4]    16384 f
    float* xs   = wbuf + 2 * KT * G4;        // [NB][DD]       2048 f  (input / pred)
    float* h0s  = xs   + NB * DD;            // [NB][HD]       4096 f
    float* h1s  = h0s  + NB * HD;            // [NB][HD]       4096 f
    float* wds  = h1s  + NB * HD;            // [HD][DD]       8192 f  (resident Wd)
    float* b0s  = wds  + HD * DD;            // [G4]
    float* b1s  = b0s  + G4;                 // [G4]
    float* bds  = b1s  + G4;                 // [DD]

    const int tid = threadIdx.x;
    const int tj0 = tid & 63;                // 64 col-threads, 2 cols/gate each
    const int tb  = tid >> 6;                // 4 row-groups, 8 rows each
    const int gb0 = blockIdx.x * NB;

    // resident weights / biases, zero states
    for (int i = tid; i < HD * DD; i += TPB) wds[i] = Wd[i];
    for (int i = tid; i < G4; i += TPB) { b0s[i] = b0[i]; b1s[i] = b1[i]; }
    if (tid < DD) bds[tid] = bd[tid];
    for (int i = tid; i < NB * HD; i += TPB) { h0s[i] = 0.0f; h1s[i] = 0.0f; }

    float c0r[8][2], c1r[8][2];
#pragma unroll
    for (int i = 0; i < 8; ++i)
#pragma unroll
        for (int j = 0; j < 2; ++j) { c0r[i][j] = 0.0f; c1r[i][j] = 0.0f; }
    __syncthreads();   // smem init visible

#pragma unroll 1
    for (int step = 0; step < NSTEPS; ++step) {
        // ---- input: warmup reads x[:, step, :]; AR phase reuses xs (= previous pred)
        // Cross-thread visibility is provided by the first tile barrier of Wk0.
        if (step < TWARM) {
#pragma unroll
            for (int i = 0; i < (NB * DD) / TPB; ++i) {
                int idx = i * TPB + tid;
                int b = idx >> 6, d = idx & 63;
                xs[idx] = x[((size_t)(gb0 + b) * TWARM + step) * DD + d];
            }
        }

        ull acc[8][4];

        // ================= layer 0 =================
        {
            ull bv[4];
#pragma unroll
            for (int g = 0; g < 4; ++g) {
                float2 b2 = *(const float2*)&b0s[g * HD + tj0 * 2];
                bv[g] = pack2(b2.x, b2.y);
            }
#pragma unroll
            for (int i = 0; i < 8; ++i)
#pragma unroll
                for (int g = 0; g < 4; ++g) acc[i][g] = bv[g];
        }
        gemm_part(acc, xs,  DD, Wk0, DD / KT, wbuf, tid, tb, tj0);   // 4 tiles
        gemm_part(acc, h0s, HD, Wr0, HD / KT, wbuf, tid, tb, tj0);   // 8 tiles
        __syncthreads();            // all old-h0 reads done before overwrite
#pragma unroll
        for (int i = 0; i < 8; ++i) {
            float2 iv = unpack2(acc[i][0]);
            float2 fv = unpack2(acc[i][1]);
            float2 gv = unpack2(acc[i][2]);
            float2 ov = unpack2(acc[i][3]);
            float cx = fmaf(sig_f(fv.x), c0r[i][0], sig_f(iv.x) * tanh_f(gv.x));
            float cy = fmaf(sig_f(fv.y), c0r[i][1], sig_f(iv.y) * tanh_f(gv.y));
            c0r[i][0] = cx; c0r[i][1] = cy;
            float2 h = make_float2(sig_f(ov.x) * tanh_f(cx), sig_f(ov.y) * tanh_f(cy));
            *(float2*)&h0s[(tb * 8 + i) * HD + tj0 * 2] = h;
        }
        // no barrier: Wk1's first tile barrier orders h0s writes before reads

        // ================= layer 1 =================
        {
            ull bv[4];
#pragma unroll
            for (int g = 0; g < 4; ++g) {
                float2 b2 = *(const float2*)&b1s[g * HD + tj0 * 2];
                bv[g] = pack2(b2.x, b2.y);
            }
#pragma unroll
            for (int i = 0; i < 8; ++i)
#pragma unroll
                for (int g = 0; g < 4; ++g) acc[i][g] = bv[g];
        }
        gemm_part(acc, h0s, HD, Wk1, HD / KT, wbuf, tid, tb, tj0);   // 8 tiles
        gemm_part(acc, h1s, HD, Wr1, HD / KT, wbuf, tid, tb, tj0);   // 8 tiles
        __syncthreads();            // all old-h1 reads done before overwrite
#pragma unroll
        for (int i = 0; i < 8; ++i) {
            float2 iv = unpack2(acc[i][0]);
            float2 fv = unpack2(acc[i][1]);
            float2 gv = unpack2(acc[i][2]);
            float2 ov = unpack2(acc[i][3]);
            float cx = fmaf(sig_f(fv.x), c1r[i][0], sig_f(iv.x) * tanh_f(gv.x));
            float cy = fmaf(sig_f(fv.y), c1r[i][1], sig_f(iv.y) * tanh_f(gv.y));
            c1r[i][0] = cx; c1r[i][1] = cy;
            float2 h = make_float2(sig_f(ov.x) * tanh_f(cx), sig_f(ov.y) * tanh_f(cy));
            *(float2*)&h1s[(tb * 8 + i) * HD + tj0 * 2] = h;
        }

        // ============ dense decode: pred = h1 @ Wd + bd (steps >= 49) ============
        if (step >= TWARM - 1) {
            __syncthreads();        // h1s writes visible before cross-thread reads
            const int s = step - (TWARM - 1);         // 0..99
            float dacc[8];
            const float bw = bds[tj0];
#pragma unroll
            for (int i = 0; i < 8; ++i) dacc[i] = bw;
#pragma unroll 4
            for (int k4 = 0; k4 < HD; k4 += 4) {
                float a[8][4];
#pragma unroll
                for (int i = 0; i < 8; ++i) {
                    float4 av = *(const float4*)&h1s[(tb * 8 + i) * HD + k4];
                    a[i][0] = av.x; a[i][1] = av.y; a[i][2] = av.z; a[i][3] = av.w;
                }
#pragma unroll
                for (int u = 0; u < 4; ++u) {
                    float w = wds[(k4 + u) * DD + tj0];
#pragma unroll
                    for (int i = 0; i < 8; ++i)
                        dacc[i] = fmaf(a[i][u], w, dacc[i]);
                }
            }
#pragma unroll
            for (int i = 0; i < 8; ++i) {
                xs[(tb * 8 + i) * DD + tj0] = dacc[i];            // feed next step
                out[((size_t)(gb0 + tb * 8 + i) * TOUT + s) * DD + tj0] = dacc[i];
            }
            // no trailing barrier: next step's first tile barrier orders xs
        }
    }
}

extern "C" void kernel_launch(void* const* d_in, const int* in_sizes, int n_in,
                              void* d_out, int out_size)
{
    const float* x   = (const float*)d_in[0];
    const float* Wk0 = (const float*)d_in[1];
    const float* Wr0 = (const float*)d_in[2];
    const float* b0  = (const float*)d_in[3];
    const float* Wk1 = (const float*)d_in[4];
    const float* Wr1 = (const float*)d_in[5];
    const float* b1  = (const float*)d_in[6];
    const float* Wd  = (const float*)d_in[7];
    const float* bd  = (const float*)d_in[8];

    size_t smem = (size_t)(2 * KT * G4 + NB * DD + 2 * NB * HD + HD * DD + 2 * G4 + DD) * sizeof(float);
    cudaFuncSetAttribute(lstm_rollout_kernel,
                         cudaFuncAttributeMaxDynamicSharedMemorySize, (int)smem);
    lstm_rollout_kernel<<<NCTA, TPB, smem>>>(x, Wk0, Wr0, b0, Wk1, Wr1, b1, Wd, bd,
                                             (float*)d_out);
}

// round 14
// speedup vs baseline: 1.8037x; 1.0252x over previous
#include <cuda_runtime.h>
#include <cstdint>

// Problem constants
#define NB     32      // batch rows per CTA
#define TPB    256     // threads per CTA (8 warps -> 2 per SMSP)
#define NCTA   128     // 128 * 32 = 4096 batch
#define HD     128     // hidden units H
#define DD     64      // latent dim D
#define G4     512     // 4*H gate width
#define KT     16      // k-tile rows for weight streaming
#define TILEF  (KT * G4)   // 8192 floats = 32KB per tile
#define TWARM  50
#define NSTEPS 149     // 50 warmup + 99 AR lstm steps
#define TOUT   100

typedef unsigned long long ull;

// ---------------- async copy helpers ----------------
__device__ __forceinline__ void cp_async16(void* dst, const void* src) {
    unsigned d = (unsigned)__cvta_generic_to_shared(dst);
    asm volatile("cp.async.cg.shared.global [%0], [%1], 16;\n" :: "r"(d), "l"(src));
}
__device__ __forceinline__ void cp_commit() { asm volatile("cp.async.commit_group;\n" ::); }
__device__ __forceinline__ void cp_wait0()  { asm volatile("cp.async.wait_group 0;\n" ::: "memory"); }

// ---------------- packed f32x2 helpers ----------------
__device__ __forceinline__ ull pack_dup(float v) {
    ull r; asm("mov.b64 %0, {%1, %1};" : "=l"(r) : "f"(v)); return r;
}
__device__ __forceinline__ ull pack2(float x, float y) {
    ull r; asm("mov.b64 %0, {%1, %2};" : "=l"(r) : "f"(x), "f"(y)); return r;
}
__device__ __forceinline__ float2 unpack2(ull p) {
    float2 r; asm("mov.b64 {%0, %1}, %2;" : "=f"(r.x), "=f"(r.y) : "l"(p)); return r;
}
__device__ __forceinline__ void fma2(ull& d, ull a, ull b) {
    asm("fma.rn.f32x2 %0, %1, %2, %0;" : "+l"(d) : "l"(a), "l"(b));
}

// ---------------- fast activations (single-MUFU tanh.approx) ----------------
__device__ __forceinline__ float tanh_f(float x) {
    float r; asm("tanh.approx.f32 %0, %1;" : "=f"(r) : "f"(x)); return r;
}
__device__ __forceinline__ float sig_f(float x) {
    return fmaf(0.5f, tanh_f(0.5f * x), 0.5f);   // exact identity, 1 MUFU
}

// Load one KT x G4 fp32 weight tile (contiguous 32KB) global -> smem via cp.async
__device__ __forceinline__ void load_tile(float* buf, const float* __restrict__ src, int tid) {
#pragma unroll
    for (int i = 0; i < TILEF / (4 * TPB); ++i) {   // 8 x 16B per thread
        int idx = (i * TPB + tid) * 4;
        cp_async16(buf + idx, src + idx);
    }
}

// acc[8][4] (f32x2 pairs) += A[NB x astride] * W(NT*KT x 512)
// thread (tb, tj0): rows tb*8 .. tb*8+7, cols { g*128 + tj0*2, +1 : g in 0..3 }
// ONE barrier per tile; prefetch issued AFTER the barrier (buffer provably drained).
// CROSS-GEMM CHAINING: this gemm's tile 0 was prefetched by the PREVIOUS gemm's
// last tile (cyclic Wk0->Wr0->Wk1->Wr1->Wk0; bootstrap load before step loop).
// All NT are even, so each gemm's tile 0 lands in buf0 -> parity is consistent.
__device__ __forceinline__ void gemm_part(
    ull acc[8][4], const float* __restrict__ As, int astride,
    const float* __restrict__ Wg, int NT, const float* __restrict__ Wnext,
    float* wbuf, int tid, int tb, int tj0)
{
#pragma unroll 1
    for (int t = 0; t < NT; ++t) {
        cp_wait0();                 // tile t landed (issued one tile-compute ago)
        __syncthreads();            // tile t visible; buf[(t+1)&1] drained by all warps
        {                           // prefetch next tile (chains into next gemm at t=NT-1)
            const float* nsrc = (t + 1 < NT) ? (Wg + (t + 1) * TILEF) : Wnext;
            load_tile(wbuf + ((t + 1) & 1) * TILEF, nsrc, tid);
            cp_commit();
        }
        const float* wt = wbuf + (t & 1) * TILEF;
        const int k0 = t * KT;
#pragma unroll
        for (int kk4 = 0; kk4 < KT; kk4 += 4) {
            float a[8][4];
#pragma unroll
            for (int i = 0; i < 8; ++i) {
                float4 av = *(const float4*)&As[(tb * 8 + i) * astride + k0 + kk4];
                a[i][0] = av.x; a[i][1] = av.y; a[i][2] = av.z; a[i][3] = av.w;
            }
#pragma unroll
            for (int u = 0; u < 4; ++u) {
                ull wv[4];
#pragma unroll
                for (int g = 0; g < 4; ++g)
                    wv[g] = *(const ull*)&wt[(kk4 + u) * G4 + g * HD + tj0 * 2];
#pragma unroll
                for (int i = 0; i < 8; ++i) {
                    ull ad = pack_dup(a[i][u]);
#pragma unroll
                    for (int g = 0; g < 4; ++g)
                        fma2(acc[i][g], ad, wv[g]);
                }
            }
        }
        // no trailing barrier: next iteration's barrier provides the drain point
    }
}

extern "C" __global__ void __launch_bounds__(TPB, 1)
lstm_rollout_kernel(const float* __restrict__ x,
                    const float* __restrict__ Wk0, const float* __restrict__ Wr0, const float* __restrict__ b0,
                    const float* __restrict__ Wk1, const float* __restrict__ Wr1, const float* __restrict__ b1,
                    const float* __restrict__ Wd,  const float* __restrict__ bd,
                    float* __restrict__ out)
{
    extern __shared__ float sm[];
    float* wbuf = sm;                        // [2][TILEF]    16384 f
    float* xs   = wbuf + 2 * TILEF;          // [NB][DD]       2048 f  (input / pred)
    float* h0s  = xs   + NB * DD;            // [NB][HD]       4096 f
    float* h1s  = h0s  + NB * HD;            // [NB][HD]       4096 f
    float* wds  = h1s  + NB * HD;            // [HD][DD]       8192 f  (resident Wd)
    float* b0s  = wds  + HD * DD;            // [G4]
    float* b1s  = b0s  + G4;                 // [G4]
    float* bds  = b1s  + G4;                 // [DD]

    const int tid = threadIdx.x;
    const int tj0 = tid & 63;                // 64 col-threads, 2 cols/gate each
    const int tb  = tid >> 6;                // 4 row-groups, 8 rows each
    const int gb0 = blockIdx.x * NB;

    // resident weights / biases, zero states
    for (int i = tid; i < HD * DD; i += TPB) wds[i] = Wd[i];
    for (int i = tid; i < G4; i += TPB) { b0s[i] = b0[i]; b1s[i] = b1[i]; }
    if (tid < DD) bds[tid] = bd[tid];
    for (int i = tid; i < NB * HD; i += TPB) { h0s[i] = 0.0f; h1s[i] = 0.0f; }

    float c0r[8][2], c1r[8][2];
#pragma unroll
    for (int i = 0; i < 8; ++i)
#pragma unroll
        for (int j = 0; j < 2; ++j) { c0r[i][j] = 0.0f; c1r[i][j] = 0.0f; }

    // bootstrap: prefetch Wk0 tile 0 into buf0 (the chain is cyclic from here on)
    load_tile(wbuf, Wk0, tid);
    cp_commit();
    __syncthreads();   // smem init visible

#pragma unroll 1
    for (int step = 0; step < NSTEPS; ++step) {
        // ---- input: warmup reads x[:, step, :]; AR phase reuses xs (= previous pred)
        // Cross-thread visibility is provided by the first tile barrier of Wk0.
        if (step < TWARM) {
#pragma unroll
            for (int i = 0; i < (NB * DD) / TPB; ++i) {
                int idx = i * TPB + tid;
                int b = idx >> 6, d = idx & 63;
                xs[idx] = x[((size_t)(gb0 + b) * TWARM + step) * DD + d];
            }
        }

        ull acc[8][4];

        // ================= layer 0 =================
        {
            ull bv[4];
#pragma unroll
            for (int g = 0; g < 4; ++g) {
                float2 b2 = *(const float2*)&b0s[g * HD + tj0 * 2];
                bv[g] = pack2(b2.x, b2.y);
            }
#pragma unroll
            for (int i = 0; i < 8; ++i)
#pragma unroll
                for (int g = 0; g < 4; ++g) acc[i][g] = bv[g];
        }
        gemm_part(acc, xs,  DD, Wk0, DD / KT, Wr0, wbuf, tid, tb, tj0);   // 4 tiles
        gemm_part(acc, h0s, HD, Wr0, HD / KT, Wk1, wbuf, tid, tb, tj0);   // 8 tiles
        __syncthreads();            // all old-h0 reads done before overwrite
#pragma unroll
        for (int i = 0; i < 8; ++i) {
            float2 iv = unpack2(acc[i][0]);
            float2 fv = unpack2(acc[i][1]);
            float2 gv = unpack2(acc[i][2]);
            float2 ov = unpack2(acc[i][3]);
            float cx = fmaf(sig_f(fv.x), c0r[i][0], sig_f(iv.x) * tanh_f(gv.x));
            float cy = fmaf(sig_f(fv.y), c0r[i][1], sig_f(iv.y) * tanh_f(gv.y));
            c0r[i][0] = cx; c0r[i][1] = cy;
            float2 h = make_float2(sig_f(ov.x) * tanh_f(cx), sig_f(ov.y) * tanh_f(cy));
            *(float2*)&h0s[(tb * 8 + i) * HD + tj0 * 2] = h;
        }
        // no barrier: Wk1's first tile barrier orders h0s writes before reads

        // ================= layer 1 =================
        {
            ull bv[4];
#pragma unroll
            for (int g = 0; g < 4; ++g) {
                float2 b2 = *(const float2*)&b1s[g * HD + tj0 * 2];
                bv[g] = pack2(b2.x, b2.y);
            }
#pragma unroll
            for (int i = 0; i < 8; ++i)
#pragma unroll
                for (int g = 0; g < 4; ++g) acc[i][g] = bv[g];
        }
        gemm_part(acc, h0s, HD, Wk1, HD / KT, Wr1, wbuf, tid, tb, tj0);   // 8 tiles
        gemm_part(acc, h1s, HD, Wr1, HD / KT, Wk0, wbuf, tid, tb, tj0);   // 8 tiles (wraps)
        __syncthreads();            // all old-h1 reads done before overwrite
#pragma unroll
        for (int i = 0; i < 8; ++i) {
            float2 iv = unpack2(acc[i][0]);
            float2 fv = unpack2(acc[i][1]);
            float2 gv = unpack2(acc[i][2]);
            float2 ov = unpack2(acc[i][3]);
            float cx = fmaf(sig_f(fv.x), c1r[i][0], sig_f(iv.x) * tanh_f(gv.x));
            float cy = fmaf(sig_f(fv.y), c1r[i][1], sig_f(iv.y) * tanh_f(gv.y));
            c1r[i][0] = cx; c1r[i][1] = cy;
            float2 h = make_float2(sig_f(ov.x) * tanh_f(cx), sig_f(ov.y) * tanh_f(cy));
            *(float2*)&h1s[(tb * 8 + i) * HD + tj0 * 2] = h;
        }

        // ============ dense decode: pred = h1 @ Wd + bd (steps >= 49) ============
        if (step >= TWARM - 1) {
            __syncthreads();        // h1s writes visible before cross-thread reads
            const int s = step - (TWARM - 1);         // 0..99
            float dacc[8];
            const float bw = bds[tj0];
#pragma unroll
            for (int i = 0; i < 8; ++i) dacc[i] = bw;
#pragma unroll 4
            for (int k4 = 0; k4 < HD; k4 += 4) {
                float a[8][4];
#pragma unroll
                for (int i = 0; i < 8; ++i) {
                    float4 av = *(const float4*)&h1s[(tb * 8 + i) * HD + k4];
                    a[i][0] = av.x; a[i][1] = av.y; a[i][2] = av.z; a[i][3] = av.w;
                }
#pragma unroll
                for (int u = 0; u < 4; ++u) {
                    float w = wds[(k4 + u) * DD + tj0];
#pragma unroll
                    for (int i = 0; i < 8; ++i)
                        dacc[i] = fmaf(a[i][u], w, dacc[i]);
                }
            }
#pragma unroll
            for (int i = 0; i < 8; ++i) {
                xs[(tb * 8 + i) * DD + tj0] = dacc[i];            // feed next step
                out[((size_t)(gb0 + tb * 8 + i) * TOUT + s) * DD + tj0] = dacc[i];
            }
            // no trailing barrier: next step's first tile barrier orders xs
        }
    }

    cp_wait0();   // drain the final (unused) prefetch before CTA exit
}

extern "C" void kernel_launch(void* const* d_in, const int* in_sizes, int n_in,
                              void* d_out, int out_size)
{
    const float* x   = (const float*)d_in[0];
    const float* Wk0 = (const float*)d_in[1];
    const float* Wr0 = (const float*)d_in[2];
    const float* b0  = (const float*)d_in[3];
    const float* Wk1 = (const float*)d_in[4];
    const float* Wr1 = (const float*)d_in[5];
    const float* b1  = (const float*)d_in[6];
    const float* Wd  = (const float*)d_in[7];
    const float* bd  = (const float*)d_in[8];

    size_t smem = (size_t)(2 * TILEF + NB * DD + 2 * NB * HD + HD * DD + 2 * G4 + DD) * sizeof(float);
    cudaFuncSetAttribute(lstm_rollout_kernel,
                         cudaFuncAttributeMaxDynamicSharedMemorySize, (int)smem);
    lstm_rollout_kernel<<<NCTA, TPB, smem>>>(x, Wk0, Wr0, b0, Wk1, Wr1, b1, Wd, bd,
                                             (float*)d_out);
}